// round 7
// baseline (speedup 1.0000x reference)
#include <cuda_runtime.h>

#define L 4096
#define DM 1024

typedef unsigned long long u64;

__device__ __forceinline__ u64 fma2(u64 a, u64 b, u64 c) {
    u64 d; asm("fma.rn.f32x2 %0, %1, %2, %3;" : "=l"(d) : "l"(a), "l"(b), "l"(c)); return d;
}
__device__ __forceinline__ u64 add2(u64 a, u64 b) {
    u64 d; asm("add.rn.f32x2 %0, %1, %2;" : "=l"(d) : "l"(a), "l"(b)); return d;
}
__device__ __forceinline__ u64 mul2(u64 a, u64 b) {
    u64 d; asm("mul.rn.f32x2 %0, %1, %2;" : "=l"(d) : "l"(a), "l"(b)); return d;
}
__device__ __forceinline__ u64 dup2(float x) {
    u64 d; asm("mov.b64 %0, {%1, %1};" : "=l"(d) : "f"(x)); return d;
}
__device__ __forceinline__ u64 sub2(u64 a, u64 b, u64 mOne) { return fma2(mOne, b, a); }

// ---- static device scratch ----
__device__ float g_tab[1088 * 128];
__device__ float g_part1[17 * 256 * DM];
__device__ float g_Fq[256 * DM];
__device__ float g_part2[8 * 256 * DM];
__device__ float g_CS[256 * DM];
__device__ float g_CS2[256 * DM];

__device__ __forceinline__ int drow(int d) {
    int g = d >> 4, i = d & 15;
    return ((g & 1)) + 2 * i + ((g >> 1) * 32);
}

__global__ void k0_basis() {
    int t = blockIdx.x;
    int i = threadIdx.x;
    float* row = &g_tab[(size_t)t * 128];
    int off = (i < 16) ? 2 * i : 32 + 2 * (i - 16);
    if (t > 1024) {
        row[off] = row[off + 1] = 0.f;
        row[64 + off] = row[64 + off + 1] = 0.f;
        return;
    }
    int k = (i < 16) ? 2 * i : 2 * (i - 16) + 1;
    int m = (k * t) & (L - 1);
    float s, c;
    sincospif((float)m / 2048.0f, &s, &c);
    row[off] = c;      row[off + 1] = c;
    row[64 + off] = s; row[64 + off + 1] = s;
}

// K1: folded forward DFT (unchanged from passing R3)
__global__ void __launch_bounds__(128) k1_fwd(const float* __restrict__ qf) {
    __shared__ __align__(16) float sm[64 * 128];
    int cblk = blockIdx.x, chunk = blockIdx.y, b = blockIdx.z;
    int tid = threadIdx.x;
    int cp = cblk * 128 + tid;
    u64 acc[64];
#pragma unroll
    for (int i = 0; i < 64; i++) acc[i] = 0ull;
    const u64 mOne = dup2(-1.0f);
    const u64 half2 = dup2(0.5f);
    const u64* qp = (const u64*)qf + (size_t)b * L * 512 + cp;
    int t0 = chunk * 64;

    const float4* src = (const float4*)&g_tab[(size_t)t0 * 128];
    float4* dst = (float4*)sm;
#pragma unroll
    for (int i = 0; i < 16; i++) dst[tid + i * 128] = src[tid + i * 128];
    __syncthreads();

    u64 n0 = qp[(size_t)t0 * 512];
    u64 n1 = qp[(size_t)(2048 - t0) * 512];
    u64 n2 = qp[(size_t)(2048 + t0) * 512];
    u64 n3 = qp[(size_t)((4096 - t0) & 4095) * 512];

    for (int tq = 0; tq < 64; tq++) {
        int t = t0 + tq;
        u64 c0 = n0, c1 = n1, c2 = n2, c3 = n3;
        if (tq < 63) {
            int tn = t + 1;
            n0 = qp[(size_t)tn * 512];
            n1 = qp[(size_t)(2048 - tn) * 512];
            n2 = qp[(size_t)(2048 + tn) * 512];
            n3 = qp[(size_t)((4096 - tn) & 4095) * 512];
        }
        u64 s03 = add2(c0, c3), d03 = sub2(c0, c3, mOne);
        u64 s12 = add2(c1, c2), d21 = sub2(c2, c1, mOne);
        u64 f[4];
        f[0] = add2(s03, s12);
        f[1] = sub2(s03, s12, mOne);
        f[2] = add2(d03, d21);
        f[3] = sub2(d03, d21, mOne);
        if (t == 0 || t == 1024) {
            f[0] = mul2(f[0], half2); f[1] = mul2(f[1], half2);
            f[2] = mul2(f[2], half2); f[3] = mul2(f[3], half2);
        }
        const ulonglong2* row = (const ulonglong2*)&sm[tq * 128];
#pragma unroll
        for (int j = 0; j < 32; j++) {
            ulonglong2 w = row[j];
            u64 fv = f[j >> 3];
            acc[2 * j]     = fma2(w.x, fv, acc[2 * j]);
            acc[2 * j + 1] = fma2(w.y, fv, acc[2 * j + 1]);
        }
    }
    u64* outp = (u64*)g_part1 + (size_t)chunk * 256 * 512 + (size_t)b * 64 * 512 + cp;
#pragma unroll
    for (int d = 0; d < 64; d++) outp[(size_t)drow(d) * 512] = acc[d];
}

__global__ void k1_reduce() {
    int i = blockIdx.x * blockDim.x + threadIdx.x;
    const float4* p = (const float4*)g_part1;
    float4 a = make_float4(0.f, 0.f, 0.f, 0.f);
#pragma unroll
    for (int ch = 0; ch < 17; ch++) {
        float4 v = p[(size_t)ch * 65536 + i];
        a.x += v.x; a.y += v.y; a.z += v.z; a.w += v.w;
    }
    ((float4*)g_Fq)[i] = a;
}

// GEMM v2: f32x2 lanes packed over OUTPUT columns j; W staged transposed.
// part2[kc][r][j] = sum_{c in 128-slab kc} A[r][c] * W[j][c]
__global__ void __launch_bounds__(128, 4) k_gemm(const float* __restrict__ W, int phase) {
    __shared__ float sA[64][34];        // [r][c]  (substage: 32 c)
    __shared__ float sW[32][132];       // [c][j]  transposed; row 528B, 16B-aligned
    const float* A = (phase == 0) ? g_Fq : g_CS;
    int jb = blockIdx.x;                // 0..7  (128 j per block)
    int rb = blockIdx.y;                // 0..3
    int kc = blockIdx.z;                // 0..7  (128 c slab)
    int tid = threadIdx.x;
    int tx = tid & 15, ty = tid >> 4;   // tx -> 8 j, ty -> 8 r
    u64 acc[8][4];
#pragma unroll
    for (int r = 0; r < 8; r++)
#pragma unroll
        for (int j = 0; j < 4; j++) acc[r][j] = 0ull;

    for (int ss = 0; ss < 4; ss++) {
        int c0 = kc * 128 + ss * 32;
        // stage A tile 64r x 32c
        for (int i = tid; i < 512; i += 128) {
            int r = i >> 3, c4 = (i & 7) * 4;
            float4 v = *(const float4*)&A[(size_t)(rb * 64 + r) * DM + c0 + c4];
            sA[r][c4] = v.x; sA[r][c4 + 1] = v.y; sA[r][c4 + 2] = v.z; sA[r][c4 + 3] = v.w;
        }
        // stage W tile transposed: 128j x 32c -> sW[c][j]
        for (int i = tid; i < 1024; i += 128) {
            int j = i >> 3, c4 = (i & 7) * 4;
            float4 v = *(const float4*)&W[(size_t)(jb * 128 + j) * DM + c0 + c4];
            sW[c4][j] = v.x; sW[c4 + 1][j] = v.y; sW[c4 + 2][j] = v.z; sW[c4 + 3][j] = v.w;
        }
        __syncthreads();
#pragma unroll 8
        for (int c = 0; c < 32; c++) {
            ulonglong2 w01 = *(const ulonglong2*)&sW[c][tx * 8];
            ulonglong2 w23 = *(const ulonglong2*)&sW[c][tx * 8 + 4];
#pragma unroll
            for (int rr = 0; rr < 8; rr++) {
                u64 ad = dup2(sA[ty * 8 + rr][c]);
                acc[rr][0] = fma2(ad, w01.x, acc[rr][0]);
                acc[rr][1] = fma2(ad, w01.y, acc[rr][1]);
                acc[rr][2] = fma2(ad, w23.x, acc[rr][2]);
                acc[rr][3] = fma2(ad, w23.y, acc[rr][3]);
            }
        }
        __syncthreads();
    }
#pragma unroll
    for (int rr = 0; rr < 8; rr++) {
        size_t base = (size_t)kc * 262144 + (size_t)(rb * 64 + ty * 8 + rr) * DM + jb * 128 + tx * 8;
        ulonglong2 v0; v0.x = acc[rr][0]; v0.y = acc[rr][1];
        ulonglong2 v1; v1.x = acc[rr][2]; v1.y = acc[rr][3];
        *(ulonglong2*)&g_part2[base]     = v0;
        *(ulonglong2*)&g_part2[base + 4] = v1;
    }
}

__global__ void k_mix(const float* __restrict__ bv, const float* __restrict__ wr_,
                      const float* __restrict__ wi_) {
    int n = blockIdx.x * blockDim.x + threadIdx.x;
    int j = n & 1023, k = (n >> 10) & 31, b = n >> 15;
    int rC = b * 64 + k, rS = rC + 32;
    float C = 0.f, S = 0.f;
#pragma unroll
    for (int kc = 0; kc < 8; kc++) {
        C += g_part2[(size_t)kc * 262144 + (size_t)rC * DM + j];
        S += g_part2[(size_t)kc * 262144 + (size_t)rS * DM + j];
    }
    if (k == 0) C += 4096.0f * bv[j];
    int h = j >> 6, d = j & 63;
    float wr = wr_[(h * 32 + k) * 64 + d];
    float wi = wi_[(h * 32 + k) * 64 + d];
    float a = (k == 0 ? 1.0f : 2.0f) * (1.0f / 4096.0f);
    g_CS[(size_t)rC * DM + j] = a * (C * wr + S * wi);
    g_CS[(size_t)rS * DM + j] = a * (S * wr - C * wi);
}

__global__ void k5_reduce() {
    int i = blockIdx.x * blockDim.x + threadIdx.x;
    const float4* p = (const float4*)g_part2;
    float4 a = make_float4(0.f, 0.f, 0.f, 0.f);
#pragma unroll
    for (int kc = 0; kc < 8; kc++) {
        float4 v = p[(size_t)kc * 65536 + i];
        a.x += v.x; a.y += v.y; a.z += v.z; a.w += v.w;
    }
    ((float4*)g_CS2)[i] = a;
}

// K4: folded expansion (unchanged from passing R3)
__global__ void __launch_bounds__(128) k4_exp(float* __restrict__ outf, const float* __restrict__ bo) {
    __shared__ __align__(16) float sm[64 * 128];
    int cblk = blockIdx.x, chunk = blockIdx.y, b = blockIdx.z;
    int tid = threadIdx.x;
    int cp = cblk * 128 + tid;
    const u64 mOne = dup2(-1.0f);
    u64 cs[64];
    const u64* csp = (const u64*)g_CS2 + (size_t)b * 64 * 512 + cp;
#pragma unroll
    for (int d = 0; d < 64; d++) cs[d] = csp[(size_t)drow(d) * 512];
    u64 bo2 = ((const u64*)bo)[cp];
    u64* outp = (u64*)outf + (size_t)b * L * 512 + cp;
    int t0 = chunk * 64;

    const float4* src = (const float4*)&g_tab[(size_t)t0 * 128];
    float4* dst = (float4*)sm;
#pragma unroll
    for (int i = 0; i < 16; i++) dst[tid + i * 128] = src[tid + i * 128];
    __syncthreads();

    for (int tq = 0; tq < 64; tq++) {
        int t = t0 + tq;
        const ulonglong2* row = (const ulonglong2*)&sm[tq * 128];
        u64 A0 = 0, A1 = 0, A2 = 0, A3 = 0;
#pragma unroll
        for (int j = 0; j < 32; j++) {
            ulonglong2 w = row[j];
            if ((j >> 3) == 0) { A0 = fma2(w.x, cs[2 * j], A0); A0 = fma2(w.y, cs[2 * j + 1], A0); }
            else if ((j >> 3) == 1) { A1 = fma2(w.x, cs[2 * j], A1); A1 = fma2(w.y, cs[2 * j + 1], A1); }
            else if ((j >> 3) == 2) { A2 = fma2(w.x, cs[2 * j], A2); A2 = fma2(w.y, cs[2 * j + 1], A2); }
            else { A3 = fma2(w.x, cs[2 * j], A3); A3 = fma2(w.y, cs[2 * j + 1], A3); }
        }
        if (t <= 1024) {
            u64 u = add2(add2(A0, A1), bo2);
            u64 v = add2(sub2(A0, A1, mOne), bo2);
            u64 w_ = add2(A2, A3);
            u64 x = sub2(A2, A3, mOne);
            outp[(size_t)t * 512]                    = add2(u, w_);
            outp[(size_t)(2048 - t) * 512]           = sub2(v, x, mOne);
            outp[(size_t)(2048 + t) * 512]           = add2(v, x);
            outp[(size_t)((4096 - t) & 4095) * 512]  = sub2(u, w_, mOne);
        }
    }
}

extern "C" void kernel_launch(void* const* d_in, const int* in_sizes, int n_in,
                              void* d_out, int out_size) {
    const float* q  = (const float*)d_in[0];
    const float* Wv = (const float*)d_in[1];
    const float* bv = (const float*)d_in[2];
    const float* Wo = (const float*)d_in[3];
    const float* bo = (const float*)d_in[4];
    const float* wr = (const float*)d_in[5];
    const float* wi = (const float*)d_in[6];
    float* out = (float*)d_out;

    k0_basis<<<1088, 32>>>();
    k1_fwd<<<dim3(4, 17, 4), 128>>>(q);
    k1_reduce<<<256, 256>>>();
    k_gemm<<<dim3(8, 4, 8), 128>>>(Wv, 0);
    k_mix<<<512, 256>>>(bv, wr, wi);
    k_gemm<<<dim3(8, 4, 8), 128>>>(Wo, 1);
    k5_reduce<<<256, 256>>>();
    k4_exp<<<dim3(4, 17, 4), 128>>>(out, bo);
}